// round 7
// baseline (speedup 1.0000x reference)
#include <cuda_runtime.h>
#include <cuda_bf16.h>
#include <cstdint>
#include <math.h>

// ===================== problem constants =====================
#define S_SCALE 64.0f
#define COS_Mc  0.8775825618903728f
#define SIN_Mc  0.479425538604203f
#define MM_Cc   0.2397127693021015f
#define TH_Cc  (-0.8775825618903728f)
#define S_LOG2E 92.33248261689366f   /* 64 * log2(e) */

constexpr int Bn = 2048;
constexpr int Dn = 512;
constexpr int Vn = 100000;
constexpr int NT = (Vn + 127) / 128;    // 782 N-tiles of 128
constexpr int NP = NT * 2;              // two partials per (row, ntile) (one per warp-col)
constexpr int PITCH = 1568;             // padded pitch (>= NP)

// ===================== device scratch (no cudaMalloc allowed) =====================
__device__ __nv_bfloat16 g_en[(size_t)Bn * Dn];     // normalized embeddings, bf16
__device__ __nv_bfloat16 g_wn[(size_t)Vn * Dn];     // normalized weight, bf16
__device__ float g_psum[(size_t)Bn * PITCH];
__device__ float g_tlog[Bn];
__device__ float g_nll[Bn];
__device__ int   g_lab64;                            // 1 if labels buffer is int64-laid-out

// ===================== small asm helpers =====================
__device__ __forceinline__ uint32_t smem_to_u32(const void* smem_ptr) {
    uint32_t addr;
    asm("{ .reg .u64 tmp; cvta.to.shared.u64 tmp, %1; cvt.u32.u64 %0, tmp; }"
        : "=r"(addr) : "l"(smem_ptr));
    return addr;
}

__device__ __forceinline__ float fast_sqrt(float x) {
    float r; asm("sqrt.approx.f32 %0, %1;" : "=f"(r) : "f"(x)); return r;
}
__device__ __forceinline__ float fast_ex2(float x) {
    float r; asm("ex2.approx.f32 %0, %1;" : "=f"(r) : "f"(x)); return r;
}

__device__ __forceinline__ void cp_async16(uint32_t dst, const void* src) {
    asm volatile("cp.async.cg.shared.global [%0], [%1], 16;" :: "r"(dst), "l"(src));
}
// zero-fill variant: src must be a valid address; src_size=0 -> 16B of zeros
__device__ __forceinline__ void cp_async16_zfill(uint32_t dst, const void* src, int src_size) {
    asm volatile("cp.async.cg.shared.global [%0], [%1], 16, %2;"
                 :: "r"(dst), "l"(src), "r"(src_size));
}
#define CP_COMMIT() asm volatile("cp.async.commit_group;" ::: "memory")
#define CP_WAIT0()  asm volatile("cp.async.wait_group 0;" ::: "memory")

__device__ __forceinline__ void ldsm_x4(uint32_t& r0, uint32_t& r1, uint32_t& r2, uint32_t& r3,
                                        uint32_t addr) {
    asm volatile("ldmatrix.sync.aligned.m8n8.x4.shared.b16 {%0,%1,%2,%3}, [%4];"
                 : "=r"(r0), "=r"(r1), "=r"(r2), "=r"(r3) : "r"(addr));
}

__device__ __forceinline__ void mma16816(float* d, const uint32_t* a, const uint32_t* b) {
    asm volatile(
        "mma.sync.aligned.m16n8k16.row.col.f32.bf16.bf16.f32 "
        "{%0,%1,%2,%3}, {%4,%5,%6,%7}, {%8,%9}, {%0,%1,%2,%3};"
        : "+f"(d[0]), "+f"(d[1]), "+f"(d[2]), "+f"(d[3])
        : "r"(a[0]), "r"(a[1]), "r"(a[2]), "r"(a[3]), "r"(b[0]), "r"(b[1]));
}

// ===================== ArcFace transform =====================
__device__ __forceinline__ float arc_logit(float c) {
    c = fminf(fmaxf(c, -1.0f), 1.0f);
    float sn = sqrtf(fmaxf(1.0f - c * c, 0.0f));
    float v = (c > TH_Cc) ? (c * COS_Mc - sn * SIN_Mc) : (c - MM_Cc);
    return S_SCALE * v;
}

// exp(S * arcface(c)); logits bounded by +-64 so no softmax-max needed
__device__ __forceinline__ float arc_exp(float c) {
    float f  = fmaf(-c, c, 1.0f);
    f        = fmaxf(f, 0.0f);
    float sn = fast_sqrt(f);
    float v1 = fmaf(c, COS_Mc, -sn * SIN_Mc);
    float v  = (c > TH_Cc) ? v1 : (c - MM_Cc);
    return fast_ex2(v * S_LOG2E);
}

// ===================== kernel 0: detect labels dtype layout =====================
// Labels are in [0, 100000) (positive, < 2^31). If the buffer is int64, the odd
// 32-bit words (high halves) of the first 2048 words are ALL zero. If int32, they
// are the odd-indexed labels (not all zero except w.p. ~1e-5120). Reading the first
// 2048 words is in-bounds for both layouts.
__global__ void __launch_bounds__(1024) detect_labels_kernel(const int* __restrict__ lw) {
    __shared__ int red[32];
    int t = threadIdx.x;
    int v = lw[2 * t + 1];
#pragma unroll
    for (int o = 16; o > 0; o >>= 1) v |= __shfl_xor_sync(0xffffffffu, v, o);
    if ((t & 31) == 0) red[t >> 5] = v;
    __syncthreads();
    if (t < 32) {
        int x = red[t];
#pragma unroll
        for (int o = 16; o > 0; o >>= 1) x |= __shfl_xor_sync(0xffffffffu, x, o);
        if (t == 0) g_lab64 = (x == 0) ? 1 : 0;
    }
}

// ===================== kernel 1/2: row L2-normalize fp32 -> bf16 =====================
__global__ void __launch_bounds__(256) norm_rows_kernel(const float* __restrict__ in,
                                                        int nrows, int which) {
    int w = (int)((blockIdx.x * blockDim.x + threadIdx.x) >> 5);
    int lid = threadIdx.x & 31;
    if (w >= nrows) return;
    __nv_bfloat16* out = which ? g_wn : g_en;

    const float4* src = reinterpret_cast<const float4*>(in + (size_t)w * Dn);
    float4 v[4];
    float ss = 0.0f;
#pragma unroll
    for (int i = 0; i < 4; i++) {
        v[i] = src[lid + 32 * i];
        ss += v[i].x * v[i].x + v[i].y * v[i].y + v[i].z * v[i].z + v[i].w * v[i].w;
    }
#pragma unroll
    for (int o = 16; o > 0; o >>= 1) ss += __shfl_xor_sync(0xffffffffu, ss, o);
    float sc = rsqrtf(fmaxf(ss, 1e-24f));

    __nv_bfloat162* op = reinterpret_cast<__nv_bfloat162*>(out + (size_t)w * Dn);
#pragma unroll
    for (int i = 0; i < 4; i++) {
        __nv_bfloat162 a = __floats2bfloat162_rn(v[i].x * sc, v[i].y * sc);
        __nv_bfloat162 b = __floats2bfloat162_rn(v[i].z * sc, v[i].w * sc);
        op[2 * (lid + 32 * i)]     = a;
        op[2 * (lid + 32 * i) + 1] = b;
    }
}

// ===================== kernel 3: target logit per sample =====================
__global__ void __launch_bounds__(256) label_logit_kernel(const int* __restrict__ labels) {
    int w = (int)((blockIdx.x * blockDim.x + threadIdx.x) >> 5);
    int lid = threadIdx.x & 31;
    if (w >= Bn) return;
    // int64 layout: low word of element w is at word index 2w (only read when the
    // buffer truly holds 2048 int64s -> 4096 words, so 2w is in-bounds).
    int lab = g_lab64 ? labels[2 * w] : labels[w];
    lab = max(0, min(Vn - 1, lab));   // defensive: never out of bounds
    const uint4* ea = reinterpret_cast<const uint4*>(g_en + (size_t)w * Dn);
    const uint4* wa = reinterpret_cast<const uint4*>(g_wn + (size_t)lab * Dn);
    float acc = 0.0f;
#pragma unroll
    for (int i = 0; i < 2; i++) {
        uint4 a = ea[lid + 32 * i];
        uint4 b = wa[lid + 32 * i];
        const __nv_bfloat162* ap = reinterpret_cast<const __nv_bfloat162*>(&a);
        const __nv_bfloat162* bp = reinterpret_cast<const __nv_bfloat162*>(&b);
#pragma unroll
        for (int j = 0; j < 4; j++) {
            float2 fa = __bfloat1622float2(ap[j]);
            float2 fb = __bfloat1622float2(bp[j]);
            acc += fa.x * fb.x + fa.y * fb.y;
        }
    }
#pragma unroll
    for (int o = 16; o > 0; o >>= 1) acc += __shfl_xor_sync(0xffffffffu, acc, o);
    if (lid == 0) g_tlog[w] = arc_logit(acc);
}

// ===================== kernel 4: main fused GEMM + partial sumexp =====================
// grid.x = NT (782), 128 threads (4 warps as 2x2, warp tile 64x64).
// W tile [128 x 512] bf16 K-resident in SMEM (row stride 1040 B -> ldmatrix conflict-free).
// A streamed in 64 k-chunks of [128 x 128] bf16, double-buffered via cp.async:
//   iter g: wait(chunk g) -> sync -> issue chunk g+1 (other buffer) -> compute chunk g.
// Per chunk: 8x k16 steps of {ldmatrix A x4, ldmatrix B x4, 32x mma.m16n8k16}.
// Per M-tile (4 chunks): in-register ArcFace exp epilogue, quad shfl reduce -> partials.
constexpr int SW_STRIDE = 1040;                      // 65 x 16B chunks per W row
constexpr int SA_STRIDE = 272;                       // 17 x 16B chunks per A row
constexpr int SW_BYTES  = 128 * SW_STRIDE;           // 133120
constexpr int SA_OFF    = SW_BYTES;                  // 16B aligned
constexpr int SA_BYTES  = 128 * SA_STRIDE;           // 34816 per buffer
constexpr int SMEM_TOTAL = SW_BYTES + 2 * SA_BYTES;  // 202752

__global__ void __launch_bounds__(128, 1) arc_main_kernel() {
    extern __shared__ char smem[];
    const uint32_t sb = smem_to_u32(smem);
    const int tid = threadIdx.x;
    const int l   = tid & 31;
    const int wid = tid >> 5;
    const int w_m = wid >> 1;            // 0..1
    const int w_n = wid & 1;             // 0..1
    const int ntile = blockIdx.x;
    const int n0 = ntile * 128;
    const bool lastTile = (n0 + 128 > Vn);

    // ---- async-load W tile [128 x 512] into SMEM (one row per thread) ----
    {
        const int r = tid;
        const bool valid = (n0 + r) < Vn;
        const char* gw = reinterpret_cast<const char*>(
            &g_wn[(size_t)(valid ? (n0 + r) : 0) * Dn]);
        const uint32_t dst = sb + (uint32_t)(r * SW_STRIDE);
        const int ssz = valid ? 16 : 0;
#pragma unroll 8
        for (int c = 0; c < 64; c++)
            cp_async16_zfill(dst + c * 16, gw + c * 16, ssz);
    }
    // ---- async-load A chunk 0 into buffer 0 ----
    {
        const char* ga = reinterpret_cast<const char*>(&g_en[(size_t)tid * Dn]);
        const uint32_t dst = sb + SA_OFF + (uint32_t)(tid * SA_STRIDE);
#pragma unroll
        for (int c = 0; c < 16; c++)
            cp_async16(dst + c * 16, ga + c * 16);
    }
    CP_COMMIT();

    // per-lane ldmatrix base addresses
    // A: lane l -> row (l&7) + 8*((l>>3)&1), k-chunk (l>>4)
    const uint32_t aBase0 = sb + SA_OFF
        + (uint32_t)(w_m * 64 + (l & 7) + 8 * ((l >> 3) & 1)) * SA_STRIDE
        + (uint32_t)(l >> 4) * 16;
    // B: lane l -> n-row (l&7) + 8*(l>>4), k-chunk ((l>>3)&1)
    const uint32_t bBase = sb
        + (uint32_t)(w_n * 64 + (l & 7) + 8 * (l >> 4)) * SW_STRIDE
        + (uint32_t)((l >> 3) & 1) * 16;

    for (int mt = 0; mt < 16; ++mt) {
        float d[4][8][4];
#pragma unroll
        for (int fm = 0; fm < 4; fm++)
#pragma unroll
            for (int nf = 0; nf < 8; nf++)
#pragma unroll
                for (int q = 0; q < 4; q++) d[fm][nf][q] = 0.0f;

        for (int kc = 0; kc < 4; ++kc) {
            const int g = mt * 4 + kc;           // global chunk index 0..63
            CP_WAIT0();                          // chunk g (and W on g==0) resident
            __syncthreads();

            // issue chunk g+1 into the other buffer (overlaps compute below)
            if (g + 1 < 64) {
                const int nmt = (g + 1) >> 2, nkc = (g + 1) & 3;
                const char* ga = reinterpret_cast<const char*>(
                    &g_en[(size_t)(nmt * 128 + tid) * Dn + nkc * 128]);
                const uint32_t dst = sb + SA_OFF + (uint32_t)(((g + 1) & 1) * SA_BYTES)
                                   + (uint32_t)(tid * SA_STRIDE);
#pragma unroll
                for (int c = 0; c < 16; c++)
                    cp_async16(dst + c * 16, ga + c * 16);
            }
            CP_COMMIT();

            const uint32_t aBase = aBase0 + (uint32_t)((g & 1) * SA_BYTES);
#pragma unroll
            for (int ks = 0; ks < 8; ++ks) {
                uint32_t a[4][4];
#pragma unroll
                for (int fm = 0; fm < 4; fm++)
                    ldsm_x4(a[fm][0], a[fm][1], a[fm][2], a[fm][3],
                            aBase + (uint32_t)(fm * 16 * SA_STRIDE) + (uint32_t)(ks * 32));
                uint32_t b[8][2];
#pragma unroll
                for (int nf2 = 0; nf2 < 4; nf2++)
                    ldsm_x4(b[2 * nf2][0], b[2 * nf2][1], b[2 * nf2 + 1][0], b[2 * nf2 + 1][1],
                            bBase + (uint32_t)(nf2 * 16 * SW_STRIDE)
                                  + (uint32_t)(kc * 256 + ks * 32));
#pragma unroll
                for (int fm = 0; fm < 4; fm++)
#pragma unroll
                    for (int nf = 0; nf < 8; nf++)
                        mma16816(d[fm][nf], a[fm], b[nf]);
            }
        }

        // ---- epilogue: ArcFace exp + row partial sums (overlaps next chunk load) ----
        // thread l holds rows (l>>2), (l>>2)+8 of each m16 frag; cols 2*(l&3)+{0,1} per n8.
#pragma unroll
        for (int fm = 0; fm < 4; fm++) {
            float sLo = 0.0f, sHi = 0.0f;
            if (!lastTile) {
#pragma unroll
                for (int nf = 0; nf < 8; nf++) {
                    sLo += arc_exp(d[fm][nf][0]) + arc_exp(d[fm][nf][1]);
                    sHi += arc_exp(d[fm][nf][2]) + arc_exp(d[fm][nf][3]);
                }
            } else {
#pragma unroll
                for (int nf = 0; nf < 8; nf++) {
                    int colb = n0 + w_n * 64 + (nf >> 1) * 16 + (nf & 1) * 8 + 2 * (l & 3);
                    if (colb < Vn)     sLo += arc_exp(d[fm][nf][0]);
                    if (colb + 1 < Vn) sLo += arc_exp(d[fm][nf][1]);
                    if (colb < Vn)     sHi += arc_exp(d[fm][nf][2]);
                    if (colb + 1 < Vn) sHi += arc_exp(d[fm][nf][3]);
                }
            }
            sLo += __shfl_xor_sync(0xffffffffu, sLo, 1);
            sLo += __shfl_xor_sync(0xffffffffu, sLo, 2);
            sHi += __shfl_xor_sync(0xffffffffu, sHi, 1);
            sHi += __shfl_xor_sync(0xffffffffu, sHi, 2);
            if ((l & 3) == 0) {
                int row = mt * 128 + w_m * 64 + fm * 16 + (l >> 2);
                g_psum[(size_t)row * PITCH + ntile * 2 + w_n]       = sLo;
                g_psum[(size_t)(row + 8) * PITCH + ntile * 2 + w_n] = sHi;
            }
        }
    }
}

// ===================== kernel 5: combine partials -> per-row NLL =====================
__global__ void __launch_bounds__(256) combine_kernel() {
    int w = (int)((blockIdx.x * blockDim.x + threadIdx.x) >> 5);
    int lid = threadIdx.x & 31;
    if (w >= Bn) return;
    const float* ps = g_psum + (size_t)w * PITCH;
    float s = 0.0f;
    for (int i = lid; i < NP; i += 32) s += ps[i];
#pragma unroll
    for (int o = 16; o > 0; o >>= 1) s += __shfl_xor_sync(0xffffffffu, s, o);
    if (lid == 0) g_nll[w] = logf(s) - g_tlog[w];
}

// ===================== kernel 6: deterministic mean =====================
__global__ void __launch_bounds__(1024) mean_kernel(float* out) {
    __shared__ float red[1024];
    int t = threadIdx.x;
    red[t] = g_nll[t] + g_nll[t + 1024];
    __syncthreads();
#pragma unroll
    for (int o = 512; o > 0; o >>= 1) {
        if (t < o) red[t] += red[t + o];
        __syncthreads();
    }
    if (t == 0) out[0] = red[0] / 2048.0f;
}

// ===================== launch =====================
extern "C" void kernel_launch(void* const* d_in, const int* in_sizes, int n_in,
                              void* d_out, int out_size) {
    const float* emb    = (const float*)d_in[0];
    const int*   labels = (const int*)d_in[1];
    const float* weight = (const float*)d_in[2];
    float*       out    = (float*)d_out;
    (void)in_sizes; (void)n_in; (void)out_size;

    cudaFuncSetAttribute(arc_main_kernel, cudaFuncAttributeMaxDynamicSharedMemorySize, SMEM_TOTAL);

    detect_labels_kernel<<<1, 1024>>>(labels);
    norm_rows_kernel<<<Bn / 8, 256>>>(emb, Bn, 0);           // 2048 rows
    norm_rows_kernel<<<Vn / 8, 256>>>(weight, Vn, 1);        // 100000 rows
    label_logit_kernel<<<Bn / 8, 256>>>(labels);
    arc_main_kernel<<<NT, 128, SMEM_TOTAL>>>();
    combine_kernel<<<Bn / 8, 256>>>();
    mean_kernel<<<1, 1024>>>(out);
}

// round 8
// speedup vs baseline: 1.2282x; 1.2282x over previous
#include <cuda_runtime.h>
#include <cuda_bf16.h>
#include <cstdint>
#include <math.h>

// ===================== problem constants =====================
#define S_SCALE 64.0f
#define COS_Mc  0.8775825618903728f
#define SIN_Mc  0.479425538604203f
#define MM_Cc   0.2397127693021015f
#define TH_Cc  (-0.8775825618903728f)
#define S_LOG2E 92.33248261689366f   /* 64 * log2(e) */

constexpr int Bn = 2048;
constexpr int Dn = 512;
constexpr int Vn = 100000;
constexpr int NT = (Vn + 127) / 128;    // 782 N-tiles of 128
constexpr int NP = NT * 2;              // two partials per (row, ntile) (one per warp-col)
constexpr int PITCH = 1568;             // padded pitch (>= NP)

// ===================== device scratch (no cudaMalloc allowed) =====================
__device__ __nv_bfloat16 g_en[(size_t)Bn * Dn];     // normalized embeddings, bf16
__device__ __nv_bfloat16 g_wn[(size_t)Vn * Dn];     // normalized weight, bf16
__device__ float g_psum[(size_t)Bn * PITCH];
__device__ float g_tlog[Bn];
__device__ float g_nll[Bn];
__device__ int   g_lab64;                            // 1 if labels buffer is int64-laid-out

// ===================== small asm helpers =====================
__device__ __forceinline__ uint32_t smem_to_u32(const void* smem_ptr) {
    uint32_t addr;
    asm("{ .reg .u64 tmp; cvta.to.shared.u64 tmp, %1; cvt.u32.u64 %0, tmp; }"
        : "=r"(addr) : "l"(smem_ptr));
    return addr;
}

__device__ __forceinline__ float fast_sqrt(float x) {
    float r; asm("sqrt.approx.f32 %0, %1;" : "=f"(r) : "f"(x)); return r;
}
__device__ __forceinline__ float fast_ex2(float x) {
    float r; asm("ex2.approx.f32 %0, %1;" : "=f"(r) : "f"(x)); return r;
}

__device__ __forceinline__ void cp_async16(uint32_t dst, const void* src) {
    asm volatile("cp.async.cg.shared.global [%0], [%1], 16;" :: "r"(dst), "l"(src));
}
// zero-fill variant: src must be a valid address; src_size=0 -> 16B of zeros
__device__ __forceinline__ void cp_async16_zfill(uint32_t dst, const void* src, int src_size) {
    asm volatile("cp.async.cg.shared.global [%0], [%1], 16, %2;"
                 :: "r"(dst), "l"(src), "r"(src_size));
}
#define CP_COMMIT() asm volatile("cp.async.commit_group;" ::: "memory")
#define CP_WAIT0()  asm volatile("cp.async.wait_group 0;" ::: "memory")

__device__ __forceinline__ void ldsm_x4(uint32_t& r0, uint32_t& r1, uint32_t& r2, uint32_t& r3,
                                        uint32_t addr) {
    asm volatile("ldmatrix.sync.aligned.m8n8.x4.shared.b16 {%0,%1,%2,%3}, [%4];"
                 : "=r"(r0), "=r"(r1), "=r"(r2), "=r"(r3) : "r"(addr));
}

__device__ __forceinline__ void mma16816(float* d, const uint32_t* a, const uint32_t* b) {
    asm volatile(
        "mma.sync.aligned.m16n8k16.row.col.f32.bf16.bf16.f32 "
        "{%0,%1,%2,%3}, {%4,%5,%6,%7}, {%8,%9}, {%0,%1,%2,%3};"
        : "+f"(d[0]), "+f"(d[1]), "+f"(d[2]), "+f"(d[3])
        : "r"(a[0]), "r"(a[1]), "r"(a[2]), "r"(a[3]), "r"(b[0]), "r"(b[1]));
}

// ===================== ArcFace transform =====================
__device__ __forceinline__ float arc_logit(float c) {
    c = fminf(fmaxf(c, -1.0f), 1.0f);
    float sn = sqrtf(fmaxf(1.0f - c * c, 0.0f));
    float v = (c > TH_Cc) ? (c * COS_Mc - sn * SIN_Mc) : (c - MM_Cc);
    return S_SCALE * v;
}

// exp(S * arcface(c)); logits bounded by +-64 so no softmax-max needed
__device__ __forceinline__ float arc_exp(float c) {
    float f  = fmaf(-c, c, 1.0f);
    f        = fmaxf(f, 0.0f);
    float sn = fast_sqrt(f);
    float v1 = fmaf(c, COS_Mc, -sn * SIN_Mc);
    float v  = (c > TH_Cc) ? v1 : (c - MM_Cc);
    return fast_ex2(v * S_LOG2E);
}

// ===================== kernel 0: detect labels dtype layout =====================
__global__ void __launch_bounds__(1024) detect_labels_kernel(const int* __restrict__ lw) {
    __shared__ int red[32];
    int t = threadIdx.x;
    int v = lw[2 * t + 1];
#pragma unroll
    for (int o = 16; o > 0; o >>= 1) v |= __shfl_xor_sync(0xffffffffu, v, o);
    if ((t & 31) == 0) red[t >> 5] = v;
    __syncthreads();
    if (t < 32) {
        int x = red[t];
#pragma unroll
        for (int o = 16; o > 0; o >>= 1) x |= __shfl_xor_sync(0xffffffffu, x, o);
        if (t == 0) g_lab64 = (x == 0) ? 1 : 0;
    }
}

// ===================== kernel 1/2: row L2-normalize fp32 -> bf16 =====================
__global__ void __launch_bounds__(256) norm_rows_kernel(const float* __restrict__ in,
                                                        int nrows, int which) {
    int w = (int)((blockIdx.x * blockDim.x + threadIdx.x) >> 5);
    int lid = threadIdx.x & 31;
    if (w >= nrows) return;
    __nv_bfloat16* out = which ? g_wn : g_en;

    const float4* src = reinterpret_cast<const float4*>(in + (size_t)w * Dn);
    float4 v[4];
    float ss = 0.0f;
#pragma unroll
    for (int i = 0; i < 4; i++) {
        v[i] = src[lid + 32 * i];
        ss += v[i].x * v[i].x + v[i].y * v[i].y + v[i].z * v[i].z + v[i].w * v[i].w;
    }
#pragma unroll
    for (int o = 16; o > 0; o >>= 1) ss += __shfl_xor_sync(0xffffffffu, ss, o);
    float sc = rsqrtf(fmaxf(ss, 1e-24f));

    __nv_bfloat162* op = reinterpret_cast<__nv_bfloat162*>(out + (size_t)w * Dn);
#pragma unroll
    for (int i = 0; i < 4; i++) {
        __nv_bfloat162 a = __floats2bfloat162_rn(v[i].x * sc, v[i].y * sc);
        __nv_bfloat162 b = __floats2bfloat162_rn(v[i].z * sc, v[i].w * sc);
        op[2 * (lid + 32 * i)]     = a;
        op[2 * (lid + 32 * i) + 1] = b;
    }
}

// ===================== kernel 3: target logit per sample =====================
__global__ void __launch_bounds__(256) label_logit_kernel(const int* __restrict__ labels) {
    int w = (int)((blockIdx.x * blockDim.x + threadIdx.x) >> 5);
    int lid = threadIdx.x & 31;
    if (w >= Bn) return;
    int lab = g_lab64 ? labels[2 * w] : labels[w];
    lab = max(0, min(Vn - 1, lab));   // defensive: never out of bounds
    const uint4* ea = reinterpret_cast<const uint4*>(g_en + (size_t)w * Dn);
    const uint4* wa = reinterpret_cast<const uint4*>(g_wn + (size_t)lab * Dn);
    float acc = 0.0f;
#pragma unroll
    for (int i = 0; i < 2; i++) {
        uint4 a = ea[lid + 32 * i];
        uint4 b = wa[lid + 32 * i];
        const __nv_bfloat162* ap = reinterpret_cast<const __nv_bfloat162*>(&a);
        const __nv_bfloat162* bp = reinterpret_cast<const __nv_bfloat162*>(&b);
#pragma unroll
        for (int j = 0; j < 4; j++) {
            float2 fa = __bfloat1622float2(ap[j]);
            float2 fb = __bfloat1622float2(bp[j]);
            acc += fa.x * fb.x + fa.y * fb.y;
        }
    }
#pragma unroll
    for (int o = 16; o > 0; o >>= 1) acc += __shfl_xor_sync(0xffffffffu, acc, o);
    if (lid == 0) g_tlog[w] = arc_logit(acc);
}

// ===================== kernel 4: main fused GEMM + partial sumexp =====================
// grid.x = NT (782), 512 threads = 16 warps in an 8m x 2n grid, warp tile 16x64.
// 4 warps per SMSP hide LDSM->HMMA latency (R7 showed 1 warp/SMSP => ~25 cyc/HMMA).
// W tile [128 x 512] bf16 K-resident in SMEM (row stride 1040 B, ldmatrix conflict-free).
// A streamed in 64 k-chunks of [128 x 128] bf16, double-buffered via cp.async.
constexpr int SW_STRIDE = 1040;                      // 65 x 16B chunks per W row
constexpr int SA_STRIDE = 272;                       // 17 x 16B chunks per A row
constexpr int SW_BYTES  = 128 * SW_STRIDE;           // 133120
constexpr int SA_OFF    = SW_BYTES;                  // 16B aligned
constexpr int SA_BYTES  = 128 * SA_STRIDE;           // 34816 per buffer
constexpr int SMEM_TOTAL = SW_BYTES + 2 * SA_BYTES;  // 202752
constexpr int MAIN_THREADS = 512;

__global__ void __launch_bounds__(MAIN_THREADS, 1) arc_main_kernel() {
    extern __shared__ char smem[];
    const uint32_t sb = smem_to_u32(smem);
    const int tid = threadIdx.x;
    const int l   = tid & 31;
    const int wid = tid >> 5;            // 0..15
    const int w_m = wid >> 1;            // 0..7  (16-row slice)
    const int w_n = wid & 1;             // 0..1  (64-col slice)
    const int ntile = blockIdx.x;
    const int n0 = ntile * 128;
    const bool lastTile = (n0 + 128 > Vn);

    // ---- async-load W tile [128 x 512]: 4 threads per row, 16 chunks each ----
    {
        const int r = tid >> 2, q = tid & 3;
        const bool valid = (n0 + r) < Vn;
        const char* gw = reinterpret_cast<const char*>(
            &g_wn[(size_t)(valid ? (n0 + r) : 0) * Dn]) + q * 256;
        const uint32_t dst = sb + (uint32_t)(r * SW_STRIDE + q * 256);
        const int ssz = valid ? 16 : 0;
#pragma unroll
        for (int c = 0; c < 16; c++)
            cp_async16_zfill(dst + c * 16, gw + c * 16, ssz);
    }
    // ---- async-load A chunk 0 into buffer 0: 4 threads per row, 4 chunks each ----
    {
        const int r = tid >> 2, q = tid & 3;
        const char* ga = reinterpret_cast<const char*>(&g_en[(size_t)r * Dn]) + q * 64;
        const uint32_t dst = sb + SA_OFF + (uint32_t)(r * SA_STRIDE + q * 64);
#pragma unroll
        for (int c = 0; c < 4; c++)
            cp_async16(dst + c * 16, ga + c * 16);
    }
    CP_COMMIT();

    // per-lane ldmatrix base addresses
    // A: warp slice rows w_m*16; lane l -> row (l&7) + 8*((l>>3)&1), k-chunk (l>>4)
    const uint32_t aBase0 = sb + SA_OFF
        + (uint32_t)(w_m * 16 + (l & 7) + 8 * ((l >> 3) & 1)) * SA_STRIDE
        + (uint32_t)(l >> 4) * 16;
    // B: lane l -> n-row (l&7) + 8*(l>>4), k-chunk ((l>>3)&1)
    const uint32_t bBase = sb
        + (uint32_t)(w_n * 64 + (l & 7) + 8 * (l >> 4)) * SW_STRIDE
        + (uint32_t)((l >> 3) & 1) * 16;

    for (int mt = 0; mt < 16; ++mt) {
        float d[8][4];
#pragma unroll
        for (int nf = 0; nf < 8; nf++)
#pragma unroll
            for (int q = 0; q < 4; q++) d[nf][q] = 0.0f;

        for (int kc = 0; kc < 4; ++kc) {
            const int g = mt * 4 + kc;           // global chunk index 0..63
            CP_WAIT0();                          // chunk g (and W on g==0) resident
            __syncthreads();

            // issue chunk g+1 into the other buffer (overlaps compute below)
            if (g + 1 < 64) {
                const int nmt = (g + 1) >> 2, nkc = (g + 1) & 3;
                const int r = tid >> 2, q = tid & 3;
                const char* ga = reinterpret_cast<const char*>(
                    &g_en[(size_t)(nmt * 128 + r) * Dn + nkc * 128]) + q * 64;
                const uint32_t dst = sb + SA_OFF + (uint32_t)(((g + 1) & 1) * SA_BYTES)
                                   + (uint32_t)(r * SA_STRIDE + q * 64);
#pragma unroll
                for (int c = 0; c < 4; c++)
                    cp_async16(dst + c * 16, ga + c * 16);
            }
            CP_COMMIT();

            const uint32_t aBase = aBase0 + (uint32_t)((g & 1) * SA_BYTES);
#pragma unroll
            for (int ks = 0; ks < 8; ++ks) {
                uint32_t a[4];
                ldsm_x4(a[0], a[1], a[2], a[3], aBase + (uint32_t)(ks * 32));
                uint32_t b[8][2];
#pragma unroll
                for (int nf2 = 0; nf2 < 4; nf2++)
                    ldsm_x4(b[2 * nf2][0], b[2 * nf2][1], b[2 * nf2 + 1][0], b[2 * nf2 + 1][1],
                            bBase + (uint32_t)(nf2 * 16 * SW_STRIDE)
                                  + (uint32_t)(kc * 256 + ks * 32));
#pragma unroll
                for (int nf = 0; nf < 8; nf++)
                    mma16816(d[nf], a, b[nf]);
            }
        }

        // ---- epilogue: ArcFace exp + row partial sums (overlaps next chunk load) ----
        // thread l holds rows (l>>2), (l>>2)+8 of the m16 frag; cols 2*(l&3)+{0,1} per n8.
        {
            float sLo = 0.0f, sHi = 0.0f;
            if (!lastTile) {
#pragma unroll
                for (int nf = 0; nf < 8; nf++) {
                    sLo += arc_exp(d[nf][0]) + arc_exp(d[nf][1]);
                    sHi += arc_exp(d[nf][2]) + arc_exp(d[nf][3]);
                }
            } else {
#pragma unroll
                for (int nf = 0; nf < 8; nf++) {
                    int colb = n0 + w_n * 64 + (nf >> 1) * 16 + (nf & 1) * 8 + 2 * (l & 3);
                    if (colb < Vn)     sLo += arc_exp(d[nf][0]);
                    if (colb + 1 < Vn) sLo += arc_exp(d[nf][1]);
                    if (colb < Vn)     sHi += arc_exp(d[nf][2]);
                    if (colb + 1 < Vn) sHi += arc_exp(d[nf][3]);
                }
            }
            sLo += __shfl_xor_sync(0xffffffffu, sLo, 1);
            sLo += __shfl_xor_sync(0xffffffffu, sLo, 2);
            sHi += __shfl_xor_sync(0xffffffffu, sHi, 1);
            sHi += __shfl_xor_sync(0xffffffffu, sHi, 2);
            if ((l & 3) == 0) {
                int row = mt * 128 + w_m * 16 + (l >> 2);
                g_psum[(size_t)row * PITCH + ntile * 2 + w_n]       = sLo;
                g_psum[(size_t)(row + 8) * PITCH + ntile * 2 + w_n] = sHi;
            }
        }
    }
}

// ===================== kernel 5: combine partials -> per-row NLL =====================
__global__ void __launch_bounds__(256) combine_kernel() {
    int w = (int)((blockIdx.x * blockDim.x + threadIdx.x) >> 5);
    int lid = threadIdx.x & 31;
    if (w >= Bn) return;
    const float* ps = g_psum + (size_t)w * PITCH;
    float s = 0.0f;
    for (int i = lid; i < NP; i += 32) s += ps[i];
#pragma unroll
    for (int o = 16; o > 0; o >>= 1) s += __shfl_xor_sync(0xffffffffu, s, o);
    if (lid == 0) g_nll[w] = logf(s) - g_tlog[w];
}

// ===================== kernel 6: deterministic mean =====================
__global__ void __launch_bounds__(1024) mean_kernel(float* out) {
    __shared__ float red[1024];
    int t = threadIdx.x;
    red[t] = g_nll[t] + g_nll[t + 1024];
    __syncthreads();
#pragma unroll
    for (int o = 512; o > 0; o >>= 1) {
        if (t < o) red[t] += red[t + o];
        __syncthreads();
    }
    if (t == 0) out[0] = red[0] / 2048.0f;
}

// ===================== launch =====================
extern "C" void kernel_launch(void* const* d_in, const int* in_sizes, int n_in,
                              void* d_out, int out_size) {
    const float* emb    = (const float*)d_in[0];
    const int*   labels = (const int*)d_in[1];
    const float* weight = (const float*)d_in[2];
    float*       out    = (float*)d_out;
    (void)in_sizes; (void)n_in; (void)out_size;

    cudaFuncSetAttribute(arc_main_kernel, cudaFuncAttributeMaxDynamicSharedMemorySize, SMEM_TOTAL);

    detect_labels_kernel<<<1, 1024>>>(labels);
    norm_rows_kernel<<<Bn / 8, 256>>>(emb, Bn, 0);           // 2048 rows
    norm_rows_kernel<<<Vn / 8, 256>>>(weight, Vn, 1);        // 100000 rows
    label_logit_kernel<<<Bn / 8, 256>>>(labels);
    arc_main_kernel<<<NT, MAIN_THREADS, SMEM_TOTAL>>>();
    combine_kernel<<<Bn / 8, 256>>>();
    mean_kernel<<<1, 1024>>>(out);
}